// round 17
// baseline (speedup 1.0000x reference)
#include <cuda_runtime.h>
#include <cuda_bf16.h>
#include <cstdint>

typedef unsigned short u16;
typedef unsigned long long u64;

#define H 512
#define DB 128
#define DC 16
#define NB 2048

// ---------------- scratch panels (bf16 x3 split, K' = 3K concatenation) ----------------
__device__ __align__(16) u16 g_A0[2048 * 1536];
__device__ __align__(16) u16 g_A1[2048 * 3072];
__device__ __align__(16) u16 g_A2[2048 * 4608];
__device__ __align__(16) u16 g_A3[2048 * 4608];
__device__ __align__(16) u16 g_A4[2048 * 3072];
__device__ __align__(16) u16 g_A5[2048 * 1536];
__device__ __align__(16) u16 g_B1[1024 * 1536];
__device__ __align__(16) u16 g_B2[1536 * 3072];
__device__ __align__(16) u16 g_BH[1536 * 4608];
__device__ __align__(16) u16 g_B3[1024 * 4608];
__device__ __align__(16) u16 g_B4[512  * 3072];
__device__ __align__(16) u16 g_B6[2048 * 1536];
__device__ __align__(16) float g_Ms[NB * DB * DC];
__device__ __align__(16) float g_outT[NB * DB];

// ---------------- helpers ----------------
__device__ __forceinline__ uint32_t smem_u32(const void* p) {
    uint32_t a;
    asm("{ .reg .u64 t; cvta.to.shared.u64 t, %1; cvt.u32.u64 %0, t; }" : "=r"(a) : "l"(p));
    return a;
}
__device__ __forceinline__ void cp16(uint32_t s, const void* g) {
    asm volatile("cp.async.cg.shared.global [%0], [%1], 16;" :: "r"(s), "l"(g) : "memory");
}
__device__ __forceinline__ void cp_commit() { asm volatile("cp.async.commit_group;" ::: "memory"); }
__device__ __forceinline__ void cp_wait1()  { asm volatile("cp.async.wait_group 1;" ::: "memory"); }
__device__ __forceinline__ void cp_wait0()  { asm volatile("cp.async.wait_group 0;" ::: "memory"); }

__device__ __forceinline__ void ldmx4(uint32_t& r0, uint32_t& r1, uint32_t& r2, uint32_t& r3,
                                      uint32_t addr)
{
    asm volatile("ldmatrix.sync.aligned.m8n8.x4.shared.b16 {%0,%1,%2,%3}, [%4];"
        : "=r"(r0), "=r"(r1), "=r"(r2), "=r"(r3) : "r"(addr));
}

__device__ __forceinline__ void mma_bf16(float* d,
    uint32_t a0, uint32_t a1, uint32_t a2, uint32_t a3, uint32_t b0, uint32_t b1)
{
    asm volatile("mma.sync.aligned.m16n8k16.row.col.f32.bf16.bf16.f32 "
        "{%0,%1,%2,%3}, {%4,%5,%6,%7}, {%8,%9}, {%0,%1,%2,%3};"
        : "+f"(d[0]), "+f"(d[1]), "+f"(d[2]), "+f"(d[3])
        : "r"(a0), "r"(a1), "r"(a2), "r"(a3), "r"(b0), "r"(b1));
}

__device__ __forceinline__ void split8(const float* x, uint4& hv, uint4& lv) {
    unsigned hs[8], ls[8];
#pragma unroll
    for (int i = 0; i < 8; i++) {
        __nv_bfloat16 h = __float2bfloat16(x[i]);
        float hf = __bfloat162float(h);
        __nv_bfloat16 l = __float2bfloat16(x[i] - hf);
        hs[i] = (unsigned)__bfloat16_as_ushort(h);
        ls[i] = (unsigned)__bfloat16_as_ushort(l);
    }
    hv.x = hs[0] | (hs[1] << 16); hv.y = hs[2] | (hs[3] << 16);
    hv.z = hs[4] | (hs[5] << 16); hv.w = hs[6] | (hs[7] << 16);
    lv.x = ls[0] | (ls[1] << 16); lv.y = ls[2] | (ls[3] << 16);
    lv.z = ls[4] | (ls[5] << 16); lv.w = ls[6] | (ls[7] << 16);
}

// ---------------- convert A: fp32 [NB,K] -> A' bf16 [NB, 3K] = [Ah|Al|Ah] ----------------
__global__ __launch_bounds__(256) void convert_A(
    const float* __restrict__ A, u16* __restrict__ P, int K)
{
    int CPR = K >> 3;
    int id = blockIdx.x * 256 + threadIdx.x;
    if (id >= NB * CPR) return;
    int r = id / CPR, c8 = id - r * CPR;
    float x[8];
    *(float4*)&x[0] = *(const float4*)&A[(size_t)r * K + c8 * 8];
    *(float4*)&x[4] = *(const float4*)&A[(size_t)r * K + c8 * 8 + 4];
    uint4 hv, lv;
    split8(x, hv, lv);
    int K3 = 3 * K;
    size_t base = (size_t)r * K3 + c8 * 8;
    *(uint4*)&P[base]         = hv;
    *(uint4*)&P[base + K]     = lv;
    *(uint4*)&P[base + 2 * K] = hv;
}

// ---------------- convert B: W fp32 [K,N] -> B' bf16 [N, 3K] = [Bh|Bh|Bl] ----------------
__global__ __launch_bounds__(256) void convert_B(
    const float* __restrict__ W, u16* __restrict__ P, int K, int N)
{
    __shared__ float ts[64][68];
    int n0 = blockIdx.x * 64, k0 = blockIdx.y * 64;
#pragma unroll
    for (int t = 0; t < 4; t++) {
        int i = threadIdx.x + t * 256;
        int row = i >> 4, q = i & 15;
        *(float4*)&ts[row][q * 4] = *(const float4*)&W[(size_t)(k0 + row) * N + n0 + q * 4];
    }
    __syncthreads();
    int K3 = 3 * K;
#pragma unroll
    for (int t = 0; t < 2; t++) {
        int s = threadIdx.x + t * 256;
        int n = s >> 3, c8 = s & 7;
        float x[8];
#pragma unroll
        for (int i = 0; i < 8; i++) x[i] = ts[c8 * 8 + i][n];
        uint4 hv, lv;
        split8(x, hv, lv);
        size_t base = (size_t)(n0 + n) * K3 + k0 + c8 * 8;
        *(uint4*)&P[base]         = hv;
        *(uint4*)&P[base + K]     = hv;
        *(uint4*)&P[base + 2 * K] = lv;
    }
}

// ---------------- bf16 mma.sync GEMM: CTA 64x64, in-CTA K-split x2, BK=32 ----------------
// 8 warps = 2 K-groups (wg) x 4 warps (2m x 2n), warp tile 32x32, acc[2][4][4].
// Each warp computes ONE k-half (ks = wg) of each BK=32 chunk -> partial sums;
// final fp32 reduction wg1 -> wg0 through smem (conflict-free transposed layout).
// 3-stage cp.async ring; stage = A 64x40 + B 64x40 u16 = 5120 u16 = 10240 B.
// smem: red area 32768 B (overlaps the 3 stages = 30720 B, reused after mainloop),
//       bias 256 B at offset 32768. Total 33024 B.
#define PADK 40
#define STG_ELEMS 5120
#define GEMM_SMEM 33024

__global__ __launch_bounds__(256, 3) void gemm_mma(
    const u16* __restrict__ A, const u16* __restrict__ B,
    const float* __restrict__ bias, int K3, int relu,
    float* __restrict__ outF, int ldF, u16* __restrict__ outP)
{
    extern __shared__ u16 dsm[];
    float* bias_s = (float*)((char*)dsm + 32768);

    const int tid = threadIdx.x;
    const int m0 = blockIdx.y * 64, n0 = blockIdx.x * 64;
    const int Nfull = gridDim.x * 64;
    const int lane = tid & 31, wid = tid >> 5;
    const int wg = wid >> 2, w4 = wid & 3;
    const int g = lane >> 2, tig = lane & 3;
    const int wm = (w4 & 1) * 32, wn = (w4 >> 1) * 32;
    const int lrow = ((lane >> 3) & 1) * 8 + (lane & 7);
    const int lcolm = (lane >> 4) * 8;

    if (tid < 64) bias_s[tid] = bias ? bias[n0 + tid] : 0.0f;

    const u16* Ag = A + (size_t)m0 * K3;
    const u16* Bg = B + (size_t)n0 * K3;

    float acc[2][4][4];
#pragma unroll
    for (int mf = 0; mf < 2; mf++)
#pragma unroll
        for (int nf = 0; nf < 4; nf++)
#pragma unroll
            for (int q = 0; q < 4; q++) acc[mf][nf][q] = 0.0f;

    const int nchunk = K3 >> 5;
    const int lr = tid >> 2;            // 0..63
    const int lc = (tid & 3) * 8;       // 4 x 16B chunks cover 32 cols

    // prefetch chunks 0,1 into stages 0,1
#pragma unroll
    for (int pf = 0; pf < 2; pf++) {
        u16* As = dsm + pf * STG_ELEMS;
        u16* Bs = As + 2560;
        int k0 = pf << 5;
        cp16(smem_u32(&As[lr * PADK + lc]), Ag + (size_t)lr * K3 + k0 + lc);
        cp16(smem_u32(&Bs[lr * PADK + lc]), Bg + (size_t)lr * K3 + k0 + lc);
        cp_commit();
    }

    const int kk = (wg << 4) + lcolm;   // this warp's fixed K-half within each chunk
    int sc = 0, si = 2;
    for (int kc = 0; kc < nchunk; kc++) {
        if (kc + 1 < nchunk) cp_wait1(); else cp_wait0();
        __syncthreads();

        if (kc + 2 < nchunk) {
            u16* As = dsm + si * STG_ELEMS;
            u16* Bs = As + 2560;
            int k0 = (kc + 2) << 5;
            cp16(smem_u32(&As[lr * PADK + lc]), Ag + (size_t)lr * K3 + k0 + lc);
            cp16(smem_u32(&Bs[lr * PADK + lc]), Bg + (size_t)lr * K3 + k0 + lc);
            cp_commit();
        }

        const u16* Asb = dsm + sc * STG_ELEMS;
        const u16* Bsb = Asb + 2560;

        uint32_t bfr[4][2];
#pragma unroll
        for (int np = 0; np < 2; np++) {
            uint32_t r0, r1, r2, r3;
            ldmx4(r0, r1, r2, r3,
                  smem_u32(&Bsb[(wn + np * 16 + lrow) * PADK + kk]));
            bfr[np * 2][0] = r0; bfr[np * 2 + 1][0] = r1;
            bfr[np * 2][1] = r2; bfr[np * 2 + 1][1] = r3;
        }
#pragma unroll
        for (int mf = 0; mf < 2; mf++) {
            uint32_t a0, a1, a2, a3;
            ldmx4(a0, a1, a2, a3,
                  smem_u32(&Asb[(wm + mf * 16 + lrow) * PADK + kk]));
#pragma unroll
            for (int nf = 0; nf < 4; nf++)
                mma_bf16(acc[mf][nf], a0, a1, a2, a3, bfr[nf][0], bfr[nf][1]);
        }

        sc = (sc == 2) ? 0 : sc + 1;
        si = (si == 2) ? 0 : si + 1;
    }

    // ---- K-split reduction: wg1 partials -> wg0 (smem, conflict-free) ----
    __syncthreads();                      // all compute done; safe to reuse stage smem
    float* red = (float*)dsm;             // 16 x 128 floats = 8192 floats = 32 KB
    const int tw = w4 * 32 + lane;        // 0..127 within k-group
    if (wg == 1) {
#pragma unroll
        for (int mf = 0; mf < 2; mf++)
#pragma unroll
            for (int nf = 0; nf < 4; nf++)
#pragma unroll
                for (int q = 0; q < 4; q++)
                    red[(mf * 16 + nf * 4 + q) * 128 + tw] = acc[mf][nf][q];
    }
    __syncthreads();
    if (wg == 0) {
#pragma unroll
        for (int mf = 0; mf < 2; mf++)
#pragma unroll
            for (int nf = 0; nf < 4; nf++)
#pragma unroll
                for (int q = 0; q < 4; q++)
                    acc[mf][nf][q] += red[(mf * 16 + nf * 4 + q) * 128 + tw];

        // ---- epilogue (wg0 only): bias + relu; fp32 out; next-layer A' panel ----
        const int K3n = 3 * Nfull;
#pragma unroll
        for (int mf = 0; mf < 2; mf++) {
#pragma unroll
            for (int hrow = 0; hrow < 2; hrow++) {
                int row = m0 + wm + mf * 16 + g + hrow * 8;
#pragma unroll
                for (int nf = 0; nf < 4; nf++) {
                    int cl = wn + nf * 8 + tig * 2;
                    float v0 = acc[mf][nf][hrow * 2 + 0] + bias_s[cl];
                    float v1 = acc[mf][nf][hrow * 2 + 1] + bias_s[cl + 1];
                    if (relu) { v0 = fmaxf(v0, 0.0f); v1 = fmaxf(v1, 0.0f); }
                    int col = n0 + cl;
                    if (outF)
                        *(float2*)&outF[(size_t)row * ldF + col] = make_float2(v0, v1);
                    if (outP) {
                        __nv_bfloat16 h0 = __float2bfloat16(v0), h1 = __float2bfloat16(v1);
                        float l0 = v0 - __bfloat162float(h0);
                        float l1 = v1 - __bfloat162float(h1);
                        __nv_bfloat16 g0 = __float2bfloat16(l0), g1 = __float2bfloat16(l1);
                        uint32_t hp = (uint32_t)__bfloat16_as_ushort(h0) |
                                      ((uint32_t)__bfloat16_as_ushort(h1) << 16);
                        uint32_t lp = (uint32_t)__bfloat16_as_ushort(g0) |
                                      ((uint32_t)__bfloat16_as_ushort(g1) << 16);
                        size_t base = (size_t)row * K3n + col;
                        *(uint32_t*)&outP[base]             = hp;
                        *(uint32_t*)&outP[base + Nfull]     = lp;
                        *(uint32_t*)&outP[base + 2 * Nfull] = hp;
                    }
                }
            }
        }
    }
}

// ---------------- packed f32x2 helpers ----------------
__device__ __forceinline__ u64 fma2_u64(u64 a, u64 b, u64 c)
{
    u64 r;
    asm("fma.rn.f32x2 %0, %1, %2, %3;" : "=l"(r) : "l"(a), "l"(b), "l"(c));
    return r;
}
__device__ __forceinline__ u64 add2_u64(u64 a, u64 b)
{
    u64 r;
    asm("add.rn.f32x2 %0, %1, %2;" : "=l"(r) : "l"(a), "l"(b));
    return r;
}

// ---------------- minibatch discrimination (symmetric, register-blocked R=4) ----------------
__global__ __launch_bounds__(128) void pairwise_sym(
    const float* __restrict__ Ms, float* __restrict__ outT)
{
    const int pair = blockIdx.x;   // 0..9
    const int b = blockIdx.y;
    int ti, tj;
    if (pair < 4)      { ti = 0; tj = pair; }
    else if (pair < 7) { ti = 1; tj = pair - 3; }
    else if (pair < 9) { ti = 2; tj = pair - 5; }
    else               { ti = 3; tj = 3; }
    const bool diag = (ti == tj);

    const int t = threadIdx.x, lane = t & 31, wid = t >> 5;
    const u64 NEG1x2 = 0xBF800000BF800000ull;
    const u64 ABSM   = 0x7FFFFFFF7FFFFFFFull;

    __shared__ u64  sj2[4][512][2];
    __shared__ float sacc[4][512];

#pragma unroll
    for (int rb = 0; rb < 4; rb++) {
        int j = rb * 128 + t;
        const float4* src = (const float4*)&Ms[(size_t)(tj * 512 + j) * 2048 + b * 16];
#pragma unroll
        for (int q = 0; q < 4; q++) {
            float4 v = src[q];
            sj2[q][j][0] = (u64)__float_as_uint(v.x) | ((u64)__float_as_uint(v.y) << 32);
            sj2[q][j][1] = (u64)__float_as_uint(v.z) | ((u64)__float_as_uint(v.w) << 32);
        }
    }
#pragma unroll
    for (int k = t; k < 4 * 512; k += 128) ((float*)sacc)[k] = 0.0f;

    u64 mi[4][8];
#pragma unroll
    for (int r = 0; r < 4; r++) {
        const float4* src = (const float4*)&Ms[(size_t)(ti * 512 + r * 128 + t) * 2048 + b * 16];
#pragma unroll
        for (int q = 0; q < 4; q++) {
            float4 v = src[q];
            mi[r][q * 2 + 0] = (u64)__float_as_uint(v.x) | ((u64)__float_as_uint(v.y) << 32);
            mi[r][q * 2 + 1] = (u64)__float_as_uint(v.z) | ((u64)__float_as_uint(v.w) << 32);
        }
    }
    float acc[4] = {0.0f, 0.0f, 0.0f, 0.0f};
    __syncthreads();

    for (int s = 0; s < 512; s++) {
        int j = (lane + s) & 511;
        u64 mj[8];
#pragma unroll
        for (int q = 0; q < 4; q++) {
            ulonglong2 v = *(const ulonglong2*)&sj2[q][j][0];
            mj[q * 2 + 0] = v.x;
            mj[q * 2 + 1] = v.y;
        }
        float esum = 0.0f;
#pragma unroll
        for (int r = 0; r < 4; r++) {
            u64 a2 = fma2_u64(mj[0], NEG1x2, mi[r][0]) & ABSM;
#pragma unroll
            for (int p = 1; p < 8; p++) {
                u64 d = fma2_u64(mj[p], NEG1x2, mi[r][p]) & ABSM;
                a2 = add2_u64(a2, d);
            }
            float lo = __uint_as_float((unsigned)(a2 & 0xffffffffu));
            float hi = __uint_as_float((unsigned)(a2 >> 32));
            float e = __expf(-(lo + hi));
            acc[r] += e;
            esum += e;
        }
        if (!diag) sacc[wid][j] += esum;
    }
    __syncthreads();

#pragma unroll
    for (int r = 0; r < 4; r++)
        atomicAdd(&outT[(size_t)(ti * 512 + r * 128 + t) * DB + b], acc[r]);
    if (!diag) {
#pragma unroll
        for (int j = t; j < 512; j += 128) {
            float v = sacc[0][j] + sacc[1][j] + sacc[2][j] + sacc[3][j];
            atomicAdd(&outT[(size_t)(tj * 512 + j) * DB + b], v);
        }
    }
}

// ---------------- final logits ----------------
__global__ __launch_bounds__(256) void final_kernel(
    const float* __restrict__ feature, const float* __restrict__ outT,
    const float* __restrict__ Wo, const float* __restrict__ bo,
    float* __restrict__ out)
{
    const int warp = threadIdx.x >> 5;
    const int lane = threadIdx.x & 31;
    const int row = blockIdx.x * 8 + warp;
    if (row >= NB) return;

    float s = 0.0f;
#pragma unroll
    for (int h = lane; h < H; h += 32)
        s = fmaf(feature[(size_t)row * H + h], Wo[h], s);
#pragma unroll
    for (int c = lane; c < DB; c += 32)
        s = fmaf(outT[(size_t)row * DB + c], Wo[H + c], s);
#pragma unroll
    for (int o = 16; o > 0; o >>= 1)
        s += __shfl_xor_sync(0xffffffffu, s, o);
    if (lane == 0) {
        float v = s + bo[0];
        out[row] = 1.0f / (1.0f + __expf(-v));
    }
}

// ---------------- launch ----------------
extern "C" void kernel_launch(void* const* d_in, const int* in_sizes, int n_in,
                              void* d_out, int out_size)
{
    const float* input = (const float*)d_in[0];
    const float* W1 = (const float*)d_in[1];
    const float* b1 = (const float*)d_in[2];
    const float* W2 = (const float*)d_in[3];
    const float* b2 = (const float*)d_in[4];
    const float* Wh = (const float*)d_in[5];
    const float* bh = (const float*)d_in[6];
    const float* W3 = (const float*)d_in[7];
    const float* b3 = (const float*)d_in[8];
    const float* W4 = (const float*)d_in[9];
    const float* b4 = (const float*)d_in[10];
    const float* Wo = (const float*)d_in[11];
    const float* bo = (const float*)d_in[12];
    const float* T  = (const float*)d_in[13];

    float* out = (float*)d_out;
    float* feature = out;
    float* logits = out + (size_t)NB * H;

    u16 *A0, *A1, *A2, *A3, *A4, *A5, *B1, *B2, *BHp, *B3p, *B4p, *B6;
    float *Ms, *oT;
    cudaGetSymbolAddress((void**)&A0, g_A0);
    cudaGetSymbolAddress((void**)&A1, g_A1);
    cudaGetSymbolAddress((void**)&A2, g_A2);
    cudaGetSymbolAddress((void**)&A3, g_A3);
    cudaGetSymbolAddress((void**)&A4, g_A4);
    cudaGetSymbolAddress((void**)&A5, g_A5);
    cudaGetSymbolAddress((void**)&B1, g_B1);
    cudaGetSymbolAddress((void**)&B2, g_B2);
    cudaGetSymbolAddress((void**)&BHp, g_BH);
    cudaGetSymbolAddress((void**)&B3p, g_B3);
    cudaGetSymbolAddress((void**)&B4p, g_B4);
    cudaGetSymbolAddress((void**)&B6, g_B6);
    cudaGetSymbolAddress((void**)&Ms, g_Ms);
    cudaGetSymbolAddress((void**)&oT, g_outT);

    cudaFuncSetAttribute(gemm_mma, cudaFuncAttributeMaxDynamicSharedMemorySize, GEMM_SMEM);

    // Profiler capture slot = my launch #4 -> gemm L1 there.
    convert_A<<<(NB * (512 / 8) + 255) / 256, 256>>>(input, A0, 512);                // #1
    convert_B<<<dim3(1024 / 64, 512 / 64),  256>>>(W1, B1, 512, 1024);               // #2
    convert_B<<<dim3(1536 / 64, 1024 / 64), 256>>>(W2, B2, 1024, 1536);              // #3
    gemm_mma<<<dim3(16, 32), 256, GEMM_SMEM>>>(A0, B1, b1, 1536, 1, nullptr, 0, A1); // #4 <- profiled
    convert_B<<<dim3(1536 / 64, 1536 / 64), 256>>>(Wh, BHp, 1536, 1536);             // #5
    convert_B<<<dim3(1024 / 64, 1536 / 64), 256>>>(W3, B3p, 1536, 1024);             // #6
    convert_B<<<dim3(512 / 64, 1024 / 64),  256>>>(W4, B4p, 1024, 512);              // #7
    convert_B<<<dim3(2048 / 64, 512 / 64),  256>>>(T, B6, 512, 2048);                // #8

    gemm_mma<<<dim3(24, 32), 256, GEMM_SMEM>>>(A1, B2,  b2, 3072, 1, nullptr, 0,    A2);
    gemm_mma<<<dim3(24, 32), 256, GEMM_SMEM>>>(A2, BHp, bh, 4608, 1, nullptr, 0,    A3);
    gemm_mma<<<dim3(16, 32), 256, GEMM_SMEM>>>(A3, B3p, b3, 4608, 1, nullptr, 0,    A4);
    gemm_mma<<<dim3(8, 32),  256, GEMM_SMEM>>>(A4, B4p, b4, 3072, 1, feature, 512,  A5);
    gemm_mma<<<dim3(32, 32), 256, GEMM_SMEM>>>(A5, B6,  nullptr, 1536, 0, Ms, 2048, nullptr);

    cudaMemsetAsync(oT, 0, (size_t)NB * DB * sizeof(float), 0);
    pairwise_sym<<<dim3(10, DB), 128>>>(Ms, oT);
    final_kernel<<<NB / 8, 256>>>(feature, oT, Wo, bo, logits);
}